// round 17
// baseline (speedup 1.0000x reference)
#include <cuda_runtime.h>
#include <cuda_bf16.h>
#include <cuda_fp16.h>
#include <cstdint>

// Problem constants
#define NN   50000
#define EE   800000
#define FIN  128
#define FHID 128
#define FOUT 64
#define SLOTS 64   // max in-degree slots per node (Poisson(16): P(deg>=64) ~ 1e-20)

// ---------------------------------------------------------------------------
// Scratch (static __device__ arrays — zero-initialized at module load).
// hs1/hs2 have ONE EXTRA ROW (index NN), never written: permanent zero row
// used as the gather target for sentinel-padded quad slots.
// ---------------------------------------------------------------------------
__device__ __half g_hs1[(size_t)(NN + 1) * FHID];  // GEMM1 out (+ zero row)
__device__ __half g_hh[(size_t)NN * FHID];         // h = relu(dis*sum + b1)
__device__ __half g_hs2[(size_t)(NN + 1) * FOUT];  // GEMM2 out (+ zero row)
__device__ int    g_cnt[NN];                       // per-node edge count
__device__ int    g_slots[(size_t)NN * SLOTS];     // direct-mapped CSR
__device__ __half g_w1h[FIN * FHID];
__device__ __half g_w2h[FHID * FOUT];

// ---------------------------------------------------------------------------
// PTX helpers
// ---------------------------------------------------------------------------
__device__ __forceinline__ uint32_t smem_u32(const void* p) {
    return (uint32_t)__cvta_generic_to_shared(p);
}

__device__ __forceinline__ void ldmat_x4(uint32_t& r0, uint32_t& r1, uint32_t& r2, uint32_t& r3,
                                         uint32_t addr) {
    asm volatile("ldmatrix.sync.aligned.m8n8.x4.shared.b16 {%0,%1,%2,%3}, [%4];"
                 : "=r"(r0), "=r"(r1), "=r"(r2), "=r"(r3) : "r"(addr));
}
__device__ __forceinline__ void ldmat_x4_t(uint32_t& r0, uint32_t& r1, uint32_t& r2, uint32_t& r3,
                                           uint32_t addr) {
    asm volatile("ldmatrix.sync.aligned.m8n8.x4.trans.shared.b16 {%0,%1,%2,%3}, [%4];"
                 : "=r"(r0), "=r"(r1), "=r"(r2), "=r"(r3) : "r"(addr));
}

__device__ __forceinline__ void mma_f16(float* d, const uint32_t* a, uint32_t b0, uint32_t b1) {
    asm volatile(
        "mma.sync.aligned.m16n8k16.row.col.f32.f16.f16.f32 "
        "{%0,%1,%2,%3}, {%4,%5,%6,%7}, {%8,%9}, {%0,%1,%2,%3};"
        : "+f"(d[0]), "+f"(d[1]), "+f"(d[2]), "+f"(d[3])
        : "r"(a[0]), "r"(a[1]), "r"(a[2]), "r"(a[3]), "r"(b0), "r"(b1));
}

// fp16x2 accumulate of TWO uint4 (16 halves) into 8 half2 accumulators
__device__ __forceinline__ void hacc8(__half2* a, uint4 v0, uint4 v1) {
    const __half2* h0 = (const __half2*)&v0;
    const __half2* h1 = (const __half2*)&v1;
    a[0] = __hadd2(a[0], h0[0]);
    a[1] = __hadd2(a[1], h0[1]);
    a[2] = __hadd2(a[2], h0[2]);
    a[3] = __hadd2(a[3], h0[3]);
    a[4] = __hadd2(a[4], h1[0]);
    a[5] = __hadd2(a[5], h1[1]);
    a[6] = __hadd2(a[6], h1[2]);
    a[7] = __hadd2(a[7], h1[3]);
}

// ---------------------------------------------------------------------------
// One-shot W conversion fp32 -> fp16
// ---------------------------------------------------------------------------
__global__ void wconv_kernel(const float* __restrict__ W1, const float* __restrict__ W2,
                             __half* __restrict__ w1h, __half* __restrict__ w2h) {
    constexpr int N1 = (FIN * FHID) / 2;
    constexpr int N2 = (FHID * FOUT) / 2;
    int i = blockIdx.x * blockDim.x + threadIdx.x;
    if (i < N1) {
        float2 v = *(const float2*)(W1 + (size_t)i * 2);
        *(__half2*)(w1h + (size_t)i * 2) = __floats2half2_rn(v.x, v.y);
    } else if (i < N1 + N2) {
        int j = i - N1;
        float2 v = *(const float2*)(W2 + (size_t)j * 2);
        *(__half2*)(w2h + (size_t)j * 2) = __floats2half2_rn(v.x, v.y);
    }
}

// ---------------------------------------------------------------------------
// Single-pass CSR build, 2 edges/thread
// ---------------------------------------------------------------------------
__global__ void fill_direct_kernel(const int* __restrict__ row, const int* __restrict__ col,
                                   int* __restrict__ cnt, int* __restrict__ slots, int e) {
    int i = blockIdx.x * blockDim.x + threadIdx.x;
    int j = i * 2;
    if (j + 1 < e) {
        int2 c = *(const int2*)(col + j);
        int2 r = *(const int2*)(row + j);
        int s0 = atomicAdd(&cnt[c.x], 1);
        int s1 = atomicAdd(&cnt[c.y], 1);
        slots[(size_t)c.x * SLOTS + s0] = r.x;
        slots[(size_t)c.y * SLOTS + s1] = r.y;
    } else if (j < e) {
        int c = col[j];
        int s = atomicAdd(&cnt[c], 1);
        slots[(size_t)c * SLOTS + s] = row[j];
    }
}

// ---------------------------------------------------------------------------
// Tensor-core GEMM, fp16 inputs, FULL K (=128) resident in smem (1 barrier):
//   out[N, F] = (x[N, 128] @ W[128, F]) * rsqrt(cnt[row]+1),  out fp16.
// BM=64, 8 warps (warp = 16-row slab x F/2 cols).
// ---------------------------------------------------------------------------
template <int F, typename TIN>
__global__ void __launch_bounds__(256)
gemm_tc_kernel(const TIN* __restrict__ x,
               const __half* __restrict__ wg,
               __half* __restrict__ out, const int* __restrict__ cnt, int nrows) {
    constexpr int BM   = 64;
    constexpr int KT   = 128;
    constexpr int NT   = F / 16;
    constexpr int ASTR = KT + 8;
    constexpr int WSTR = F + 8;

    extern __shared__ __half smem[];
    __half* Ah = smem;
    __half* Wh = Ah + BM * ASTR;

    const int tid  = threadIdx.x;
    const int lane = tid & 31;
    const int w    = tid >> 5;
    const int slab = w >> 1;
    const int ch   = w & 1;
    const int row0 = blockIdx.x * BM;

    float acc[NT][4];
#pragma unroll
    for (int nt = 0; nt < NT; nt++)
#pragma unroll
        for (int j = 0; j < 4; j++) acc[nt][j] = 0.f;

    const int mat  = lane >> 3;
    const int mrow = lane & 7;

    if constexpr (sizeof(TIN) == 4) {
        constexpr int NV = (BM * KT) / 4;
#pragma unroll
        for (int p = tid; p < NV; p += 256) {
            int r  = p / (KT / 4);
            int kq = (p % (KT / 4)) * 4;
            float4 v;
            int grow = row0 + r;
            if (grow < nrows)
                v = *(const float4*)((const float*)x + (size_t)grow * FIN + kq);
            else
                v = make_float4(0.f, 0.f, 0.f, 0.f);
            *(__half2*)(Ah + r * ASTR + kq)     = __floats2half2_rn(v.x, v.y);
            *(__half2*)(Ah + r * ASTR + kq + 2) = __floats2half2_rn(v.z, v.w);
        }
    } else {
        constexpr int NV = (BM * KT) / 8;
#pragma unroll
        for (int p = tid; p < NV; p += 256) {
            int r  = p / (KT / 8);
            int kq = (p % (KT / 8)) * 8;
            uint4 v;
            int grow = row0 + r;
            if (grow < nrows)
                v = *(const uint4*)((const __half*)x + (size_t)grow * FIN + kq);
            else
                v = make_uint4(0, 0, 0, 0);
            *(uint4*)(Ah + r * ASTR + kq) = v;
        }
    }
    {
        constexpr int NV = (KT * F) / 8;
#pragma unroll
        for (int p = tid; p < NV; p += 256) {
            int k = p / (F / 8);
            int c = (p % (F / 8)) * 8;
            *(uint4*)(Wh + k * WSTR + c) = *(const uint4*)(wg + (size_t)k * F + c);
        }
    }
    __syncthreads();

#pragma unroll
    for (int ks = 0; ks < KT / 16; ks++) {
        uint32_t ah[4];
        {
            int arow = slab * 16 + (mat & 1) * 8 + mrow;
            int acol = ks * 16 + (mat >> 1) * 8;
            ldmat_x4(ah[0], ah[1], ah[2], ah[3], smem_u32(Ah + arow * ASTR + acol));
        }
#pragma unroll
        for (int nt2 = 0; nt2 < NT / 2; nt2++) {
            int krow = ks * 16 + (mat & 1) * 8 + mrow;
            int ncol = ch * (F / 2) + nt2 * 16 + (mat >> 1) * 8;
            uint32_t bh[4];
            ldmat_x4_t(bh[0], bh[1], bh[2], bh[3], smem_u32(Wh + krow * WSTR + ncol));
            mma_f16(acc[2 * nt2],     ah, bh[0], bh[1]);
            mma_f16(acc[2 * nt2 + 1], ah, bh[2], bh[3]);
        }
    }

    {
        int r0 = row0 + slab * 16 + (lane >> 2);
        int r1 = r0 + 8;
        float s0 = (r0 < nrows) ? rsqrtf((float)__ldg(cnt + r0) + 1.0f) : 0.f;
        float s1 = (r1 < nrows) ? rsqrtf((float)__ldg(cnt + r1) + 1.0f) : 0.f;
        int cbase = ch * (F / 2) + (lane & 3) * 2;
#pragma unroll
        for (int nt = 0; nt < NT; nt++) {
            int c = cbase + nt * 8;
            if (r0 < nrows)
                *(__half2*)(out + (size_t)r0 * F + c) = __floats2half2_rn(acc[nt][0] * s0, acc[nt][1] * s0);
            if (r1 < nrows)
                *(__half2*)(out + (size_t)r1 * F + c) = __floats2half2_rn(acc[nt][2] * s1, acc[nt][3] * s1);
        }
    }
}

// ---------------------------------------------------------------------------
// Segment-sum aggregate, 32 BYTES (16 halves) PER THREAD per row:
// halves the thread count and amortizes address math / slot SELs / loop
// bookkeeping over 2x the data (the kernel is instruction-issue bound, not
// occupancy bound — proven R15 vs R16). 2 ILP chains x 2 rows per quad.
// Sentinel zero-row (index n) pads the last quad — no scalar tail.
// ---------------------------------------------------------------------------
template <int F, bool RELU, typename TOUT>
__global__ void __launch_bounds__(256, 4)
aggregate_kernel(const __half* __restrict__ hs,
                 const int* __restrict__ slots, const int* __restrict__ cnt,
                 const float* __restrict__ bias,
                 TOUT* __restrict__ out, int n) {
    constexpr int LPN = F / 16;                // threads per node
    const int gtid = blockIdx.x * blockDim.x + threadIdx.x;
    const int node = gtid / LPN;
    const int sub  = gtid % LPN;
    if (node >= n) return;

    const int deg = __ldg(cnt + node);
    const int beg = node * SLOTS;
    const int fo  = sub * 16;                  // feature offset (halves)

    __half2 a0[8], a1[8];
    // self loop seeds a0; a1 zero
    {
        const __half* p = hs + (size_t)node * F + fo;
        uint4 s0 = *(const uint4*)(p);
        uint4 s1 = *(const uint4*)(p + 8);
        const __half2* h0 = (const __half2*)&s0;
        const __half2* h1 = (const __half2*)&s1;
        __half2 z = __floats2half2_rn(0.f, 0.f);
#pragma unroll
        for (int j = 0; j < 4; j++) { a0[j] = h0[j]; a0[j + 4] = h1[j]; a1[j] = z; a1[j + 4] = z; }
    }

    const int nq = (deg + 3) >> 2;             // sentinel-padded quads
    for (int q = 0; q < nq; q++) {
        int4 s = *(const int4*)(slots + beg + q * 4);   // aligned (beg % 64 == 0)
        int p = q * 4;
        int r0 = s.x;
        int r1 = (p + 1 < deg) ? s.y : n;      // n = zero sentinel row
        int r2 = (p + 2 < deg) ? s.z : n;
        int r3 = (p + 3 < deg) ? s.w : n;
        const __half* p0 = hs + (size_t)r0 * F + fo;
        const __half* p1 = hs + (size_t)r1 * F + fo;
        const __half* p2 = hs + (size_t)r2 * F + fo;
        const __half* p3 = hs + (size_t)r3 * F + fo;
        uint4 v0a = *(const uint4*)(p0);
        uint4 v0b = *(const uint4*)(p0 + 8);
        uint4 v1a = *(const uint4*)(p1);
        uint4 v1b = *(const uint4*)(p1 + 8);
        uint4 v2a = *(const uint4*)(p2);
        uint4 v2b = *(const uint4*)(p2 + 8);
        uint4 v3a = *(const uint4*)(p3);
        uint4 v3b = *(const uint4*)(p3 + 8);
        hacc8(a0, v0a, v0b);
        hacc8(a1, v1a, v1b);
        hacc8(a0, v2a, v2b);
        hacc8(a1, v3a, v3b);
    }

    // fp32 final combine
    const float d = rsqrtf((float)deg + 1.0f);
    float o[16];
#pragma unroll
    for (int j = 0; j < 8; j++) {
        float2 f0 = __half22float2(a0[j]);
        float2 f1 = __half22float2(a1[j]);
        o[2 * j]     = f0.x + f1.x;
        o[2 * j + 1] = f0.y + f1.y;
    }
#pragma unroll
    for (int g = 0; g < 4; g++) {
        float4 bv = *(const float4*)(bias + fo + g * 4);
#pragma unroll
        for (int j = 0; j < 4; j++) {
            float v = o[g * 4 + j] * d + ((const float*)&bv)[j];
            if (RELU) v = fmaxf(v, 0.f);
            o[g * 4 + j] = v;
        }
    }

    if constexpr (sizeof(TOUT) == 2) {
        __half2 pk[8];
#pragma unroll
        for (int j = 0; j < 8; j++) pk[j] = __floats2half2_rn(o[2 * j], o[2 * j + 1]);
        __half* op = (__half*)out + (size_t)node * F + fo;
        *(uint4*)(op)     = *(uint4*)(pk);
        *(uint4*)(op + 8) = *(uint4*)(pk + 4);
    } else {
        float* op = (float*)out + (size_t)node * F + fo;
        *(float4*)(op)      = make_float4(o[0],  o[1],  o[2],  o[3]);
        *(float4*)(op + 4)  = make_float4(o[4],  o[5],  o[6],  o[7]);
        *(float4*)(op + 8)  = make_float4(o[8],  o[9],  o[10], o[11]);
        *(float4*)(op + 12) = make_float4(o[12], o[13], o[14], o[15]);
    }
}

// ---------------------------------------------------------------------------
// Launch: side stream only for memset+fill (overlaps wconv); join before
// GEMM1 (its epilogue reads cnt). Sequential otherwise.
// ---------------------------------------------------------------------------
extern "C" void kernel_launch(void* const* d_in, const int* in_sizes, int n_in,
                              void* d_out, int out_size) {
    const float* x  = (const float*)d_in[0];
    const int*   ei = (const int*)d_in[1];
    const float* W1 = (const float*)d_in[2];
    const float* b1 = (const float*)d_in[3];
    const float* W2 = (const float*)d_in[4];
    const float* b2 = (const float*)d_in[5];
    float* out = (float*)d_out;

    const int* row = ei;
    const int* col = ei + EE;

    constexpr int SMEM1 = (64 * 136 + 128 * 136) * 2;  // 52,224 B (F=128)
    constexpr int SMEM2 = (64 * 136 + 128 * 72) * 2;   // 35,840 B (F=64)

    static __half *p_hs1 = nullptr, *p_hh = nullptr, *p_hs2 = nullptr,
                  *p_w1h = nullptr, *p_w2h = nullptr;
    static int *p_cnt = nullptr, *p_slots = nullptr;
    static cudaStream_t s_side = nullptr;
    static cudaEvent_t s_fork = nullptr, s_join = nullptr;
    if (!p_hs1) {
        cudaGetSymbolAddress((void**)&p_hs1,   g_hs1);
        cudaGetSymbolAddress((void**)&p_hh,    g_hh);
        cudaGetSymbolAddress((void**)&p_hs2,   g_hs2);
        cudaGetSymbolAddress((void**)&p_cnt,   g_cnt);
        cudaGetSymbolAddress((void**)&p_slots, g_slots);
        cudaGetSymbolAddress((void**)&p_w1h,   g_w1h);
        cudaGetSymbolAddress((void**)&p_w2h,   g_w2h);
        cudaFuncSetAttribute((const void*)gemm_tc_kernel<128, float>,
                             cudaFuncAttributeMaxDynamicSharedMemorySize, SMEM1);
        cudaFuncSetAttribute((const void*)gemm_tc_kernel<64, __half>,
                             cudaFuncAttributeMaxDynamicSharedMemorySize, SMEM2);
        cudaStreamCreateWithFlags(&s_side, cudaStreamNonBlocking);
        cudaEventCreateWithFlags(&s_fork, cudaEventDisableTiming);
        cudaEventCreateWithFlags(&s_join, cudaEventDisableTiming);
    }

    const int GBLK = (NN + 63) / 64;       // 782

    // ---- fork: CSR build on side stream (overlaps wconv) ----
    cudaEventRecord(s_fork, 0);
    cudaStreamWaitEvent(s_side, s_fork, 0);
    cudaMemsetAsync(p_cnt, 0, (size_t)NN * sizeof(int), s_side);
    fill_direct_kernel<<<(EE / 2 + 255) / 256, 256, 0, s_side>>>(row, col, p_cnt, p_slots, EE);
    cudaEventRecord(s_join, s_side);

    // ---- main: W conversion ----
    {
        constexpr int NPAIR = (FIN * FHID + FHID * FOUT) / 2;
        wconv_kernel<<<(NPAIR + 255) / 256, 256>>>(W1, W2, p_w1h, p_w2h);
    }
    // gemm1 epilogue reads cnt — join here
    cudaStreamWaitEvent(0, s_join, 0);
    gemm_tc_kernel<128, float><<<GBLK, 256, SMEM1>>>(x, p_w1h, p_hs1, p_cnt, NN);

    // ---- layer 1 aggregate -> h (fp16) ----
    {
        long long threads = (long long)NN * (FHID / 16);   // 400k
        aggregate_kernel<128, true, __half><<<(int)((threads + 255) / 256), 256>>>(
            p_hs1, p_slots, p_cnt, b1, p_hh, NN);
    }

    // ---- layer 2: fp16 tensor GEMM ----
    gemm_tc_kernel<64, __half><<<GBLK, 256, SMEM2>>>(p_hh, p_w2h, p_hs2, p_cnt, NN);

    // ---- layer 2 aggregate -> d_out (fp32) ----
    {
        long long threads = (long long)NN * (FOUT / 16);   // 200k
        aggregate_kernel<64, false, float><<<(int)((threads + 255) / 256), 256>>>(
            p_hs2, p_slots, p_cnt, b2, out, NN);
    }
}